// round 1
// baseline (speedup 1.0000x reference)
#include <cuda_runtime.h>
#include <math.h>

#define B_SZ   2048
#define T_SZ   60
#define F_SZ   89
#define H_SZ   1024
#define G4H    4096
#define OUT_SZ 30

// Scratch state (device globals — no runtime allocation).
__device__ float g_z[(size_t)B_SZ * G4H];   // 32 MB: pre-activation gates for current step
__device__ float g_h[(size_t)B_SZ * H_SZ];  // 8 MB
__device__ float g_c[(size_t)B_SZ * H_SZ];  // 8 MB

// ---------------------------------------------------------------------------
// Zero h and c at the start of every launch (graph-replay deterministic).
// ---------------------------------------------------------------------------
__global__ void init_state_kernel() {
    int idx = blockIdx.x * blockDim.x + threadIdx.x;
    if (idx < B_SZ * H_SZ) {
        g_h[idx] = 0.0f;
        g_c[idx] = 0.0f;
    }
}

// ---------------------------------------------------------------------------
// Step GEMM: z = x[:, t, :] @ W  +  h @ U  +  b     -> g_z  [B, 4H]
// 128x128 blocktile, 8x8 per-thread microtile, BK=8, 256 threads.
// ---------------------------------------------------------------------------
#define BM 128
#define BN 128
#define BK 8
#define TM 8
#define TN 8

__global__ __launch_bounds__(256) void step_gemm_kernel(
    const float* __restrict__ x,
    const float* __restrict__ W,
    const float* __restrict__ U,
    const float* __restrict__ bias,
    int t)
{
    __shared__ float As[BK][BM];
    __shared__ float Bs[BK][BN];

    const int tid    = threadIdx.x;
    const int blockM = blockIdx.y * BM;
    const int blockN = blockIdx.x * BN;
    const int tx     = tid & 15;   // 0..15
    const int ty     = tid >> 4;   // 0..15

    // A-tile load mapping: 128 rows x 8 cols, 4 consecutive K per thread
    const int aRow = tid >> 1;         // 0..127
    const int aCol = (tid & 1) * 4;    // 0 or 4
    // B-tile load mapping: 8 rows x 128 cols, 4 consecutive N per thread
    const int bRow = tid >> 5;         // 0..7
    const int bCol = (tid & 31) * 4;   // 0..124

    float acc[TM][TN];
#pragma unroll
    for (int i = 0; i < TM; i++)
#pragma unroll
        for (int j = 0; j < TN; j++) acc[i][j] = 0.0f;

    // ---------------- Part 1: x_t @ W  (K = 89, guarded) ----------------
    for (int k0 = 0; k0 < F_SZ; k0 += BK) {
        // A = x[:, t, :] ; element (m, k) at x[(m*T + t)*F + k]
#pragma unroll
        for (int i = 0; i < 4; i++) {
            int k = k0 + aCol + i;
            As[aCol + i][aRow] = (k < F_SZ)
                ? x[((size_t)(blockM + aRow) * T_SZ + t) * F_SZ + k]
                : 0.0f;
        }
        {
            int k = k0 + bRow;
            if (k < F_SZ) {
                float4 bv = *reinterpret_cast<const float4*>(
                    &W[(size_t)k * G4H + blockN + bCol]);
                Bs[bRow][bCol + 0] = bv.x;
                Bs[bRow][bCol + 1] = bv.y;
                Bs[bRow][bCol + 2] = bv.z;
                Bs[bRow][bCol + 3] = bv.w;
            } else {
                Bs[bRow][bCol + 0] = 0.0f;
                Bs[bRow][bCol + 1] = 0.0f;
                Bs[bRow][bCol + 2] = 0.0f;
                Bs[bRow][bCol + 3] = 0.0f;
            }
        }
        __syncthreads();
#pragma unroll
        for (int kk = 0; kk < BK; kk++) {
            float a[TM], b[TN];
#pragma unroll
            for (int i = 0; i < TM; i++) a[i] = As[kk][ty * TM + i];
#pragma unroll
            for (int j = 0; j < TN; j++) b[j] = Bs[kk][tx * TN + j];
#pragma unroll
            for (int i = 0; i < TM; i++)
#pragma unroll
                for (int j = 0; j < TN; j++) acc[i][j] += a[i] * b[j];
        }
        __syncthreads();
    }

    // ---------------- Part 2: h @ U  (K = 1024, unguarded) ----------------
    for (int k0 = 0; k0 < H_SZ; k0 += BK) {
        {
            float4 av = *reinterpret_cast<const float4*>(
                &g_h[(size_t)(blockM + aRow) * H_SZ + k0 + aCol]);
            As[aCol + 0][aRow] = av.x;
            As[aCol + 1][aRow] = av.y;
            As[aCol + 2][aRow] = av.z;
            As[aCol + 3][aRow] = av.w;
        }
        {
            float4 bv = *reinterpret_cast<const float4*>(
                &U[(size_t)(k0 + bRow) * G4H + blockN + bCol]);
            Bs[bRow][bCol + 0] = bv.x;
            Bs[bRow][bCol + 1] = bv.y;
            Bs[bRow][bCol + 2] = bv.z;
            Bs[bRow][bCol + 3] = bv.w;
        }
        __syncthreads();
#pragma unroll
        for (int kk = 0; kk < BK; kk++) {
            float a[TM], b[TN];
#pragma unroll
            for (int i = 0; i < TM; i++) a[i] = As[kk][ty * TM + i];
#pragma unroll
            for (int j = 0; j < TN; j++) b[j] = Bs[kk][tx * TN + j];
#pragma unroll
            for (int i = 0; i < TM; i++)
#pragma unroll
                for (int j = 0; j < TN; j++) acc[i][j] += a[i] * b[j];
        }
        __syncthreads();
    }

    // ---------------- Epilogue: add bias, write z ----------------
#pragma unroll
    for (int i = 0; i < TM; i++) {
        float* zr = &g_z[(size_t)(blockM + ty * TM + i) * G4H + blockN + tx * TN];
        const float* br = &bias[blockN + tx * TN];
#pragma unroll
        for (int j = 0; j < TN; j += 4) {
            float4 v;
            v.x = acc[i][j + 0] + br[j + 0];
            v.y = acc[i][j + 1] + br[j + 1];
            v.z = acc[i][j + 2] + br[j + 2];
            v.w = acc[i][j + 3] + br[j + 3];
            *reinterpret_cast<float4*>(&zr[j]) = v;
        }
    }
}

// ---------------------------------------------------------------------------
// Gate / state update. Keras gate order: i, f, g(candidate), o.
// c = sigmoid(f)*c + sigmoid(i)*relu(g);  h = sigmoid(o)*relu(c)
// ---------------------------------------------------------------------------
__device__ __forceinline__ float sigmoidf_(float v) {
    return 1.0f / (1.0f + expf(-v));
}

__global__ void gate_kernel() {
    int idx = blockIdx.x * blockDim.x + threadIdx.x;
    if (idx >= B_SZ * H_SZ) return;
    int m = idx >> 10;        // / H_SZ
    int j = idx & (H_SZ - 1); // % H_SZ
    const float* zr = g_z + (size_t)m * G4H;
    float zi = zr[j];
    float zf = zr[H_SZ + j];
    float zg = zr[2 * H_SZ + j];
    float zo = zr[3 * H_SZ + j];

    float ig = sigmoidf_(zi);
    float fg = sigmoidf_(zf);
    float gg = fmaxf(zg, 0.0f);
    float og = sigmoidf_(zo);

    float c = fg * g_c[idx] + ig * gg;
    g_c[idx] = c;
    g_h[idx] = og * fmaxf(c, 0.0f);
}

// ---------------------------------------------------------------------------
// Dense head: y = h_T @ Wd + bd   ([2048,1024] @ [1024,30])
// ---------------------------------------------------------------------------
__global__ void dense_kernel(const float* __restrict__ Wd,
                             const float* __restrict__ bd,
                             float* __restrict__ out)
{
    int m = blockIdx.x;
    int o = threadIdx.x;
    if (o >= OUT_SZ) return;
    const float* hr = g_h + (size_t)m * H_SZ;
    float acc = bd[o];
#pragma unroll 4
    for (int k = 0; k < H_SZ; k++)
        acc = fmaf(hr[k], Wd[(size_t)k * OUT_SZ + o], acc);
    out[(size_t)m * OUT_SZ + o] = acc;
}

// ---------------------------------------------------------------------------
extern "C" void kernel_launch(void* const* d_in, const int* in_sizes, int n_in,
                              void* d_out, int out_size)
{
    const float* x  = (const float*)d_in[0];  // [B, T, F]
    const float* W  = (const float*)d_in[1];  // [F, 4H]
    const float* U  = (const float*)d_in[2];  // [H, 4H]
    const float* b  = (const float*)d_in[3];  // [4H]
    const float* Wd = (const float*)d_in[4];  // [H, OUT]
    const float* bd = (const float*)d_in[5];  // [OUT]
    float* out = (float*)d_out;               // [B, OUT, 1]

    init_state_kernel<<<(B_SZ * H_SZ + 255) / 256, 256>>>();

    dim3 grid(G4H / BN, B_SZ / BM);  // 32 x 16 = 512 blocks
    for (int t = 0; t < T_SZ; t++) {
        step_gemm_kernel<<<grid, 256>>>(x, W, U, b, t);
        gate_kernel<<<(B_SZ * H_SZ + 255) / 256, 256>>>();
    }

    dense_kernel<<<B_SZ, 32>>>(Wd, bd, out);
}